// round 7
// baseline (speedup 1.0000x reference)
#include <cuda_runtime.h>
#include <cstdint>

// Problem constants
static constexpr int Lc  = 32;
static constexpr int Kc  = 4;
static constexpr int Dc  = 1024;
static constexpr int QOc = 1024;
static constexpr int KVc = 256;
static constexpr int FFc = 2816;

static constexpr int S        = 128;          // stage width (floats)
static constexpr int ROWS_BLK = 16;           // d-rows per block
static constexpr int RW       = 4;            // rows per warp (row-group)
static constexpr int CSLOT_F  = 12 * S;       // cursed slot (max M = 12), floats
static constexpr int NSLOT    = 4;            // ring slots (6 KB each -> 24 KB)

typedef unsigned long long ull;

// ---------------- f32x2 packed FMA (sm_103a) ----------------
__device__ __forceinline__ void ffma2(ull& acc, ull a, ull b) {
    asm("fma.rn.f32x2 %0, %1, %2, %0;" : "+l"(acc) : "l"(a), "l"(b));
}
__device__ __forceinline__ float hsum2(ull v) {
    return __uint_as_float((uint32_t)v) + __uint_as_float((uint32_t)(v >> 32));
}

// ---------------- cp.async helpers ----------------
__device__ __forceinline__ void cp_async16(uint32_t saddr, const void* gptr) {
    asm volatile("cp.async.cg.shared.global [%0], [%1], 16;" :: "r"(saddr), "l"(gptr));
}
__device__ __forceinline__ void cp_commit() {
    asm volatile("cp.async.commit_group;");
}
template<int N>
__device__ __forceinline__ void cp_wait() {
    asm volatile("cp.async.wait_group %0;" :: "n"(N));
}

// Stage M x S floats of cursed data (cols [c0,c0+S)) into a ring slot. 256 thr.
template<int M, int I>
__device__ __forceinline__ void stage_cursed(uint32_t sbuf, const float* __restrict__ Cl,
                                             int c0, int tid)
{
#pragma unroll
    for (int idx = tid; idx < M * (S / 4); idx += 256) {
        const int j   = idx >> 5;          // S/4 = 32 transfers per vec
        const int c16 = idx & 31;
        cp_async16(sbuf + (uint32_t)(j * S + c16 * 4) * 4u,
                   Cl + (size_t)j * I + c0 + c16 * 4);
    }
}

// Load this warp's 4 weight rows for one stage (1 LDG.128 per row) into regs.
template<int I>
__device__ __forceinline__ void load_w(ull w01[RW], ull w23[RW],
                                       const float* __restrict__ wlane, int c0)
{
#pragma unroll
    for (int t = 0; t < RW; ++t) {
        const double2 wd = __ldcg(reinterpret_cast<const double2*>(
            wlane + (size_t)t * I + c0));
        w01[t] = __double_as_longlong(wd.x);
        w23[t] = __double_as_longlong(wd.y);
    }
}

// ---------------- projection tile ----------------
// Block: 256 threads = 8 warps = 4 row-groups(4 rows) x 2 M-groups(M/2 vecs).
// Weights: register-double-buffered direct LDG (stage s issued during s-1),
//          each line touched by exactly 2 warps (1 DRAM + 1 L1 hit).
// Cursed:  cp.async 4-slot ring, distance-3 lookahead, uniform commits.
template<int M, int I, bool IS_MLP, int MFIX>
__device__ __forceinline__ void proj_tile(
    const float* __restrict__ Wl,   // layer weight [D][I]
    const float* __restrict__ Cl,   // layer cursed vecs [M][I]
    float* __restrict__ out,
    float* __restrict__ smem,       // [NSLOT][CSLOT_F]
    int l, int d0)
{
    constexpr int MGV = M / 2;      // vecs per warp
    const int tid   = threadIdx.x;
    const int lane  = tid & 31;
    const int warp  = tid >> 5;
    const int rg    = warp >> 1;    // row-group 0..3
    const int g     = warp & 1;     // M-group 0/1
    const int dbase = d0 + rg * RW;
    const uint32_t smem_u32 = (uint32_t)__cvta_generic_to_shared(smem);
    constexpr int NS = I / S;
    constexpr uint32_t SLOTB = (uint32_t)(CSLOT_F * 4);

    ull acc2[RW][MGV];
#pragma unroll
    for (int t = 0; t < RW; ++t)
#pragma unroll
        for (int j = 0; j < MGV; ++j) acc2[t][j] = 0ull;

    const float* wlane = Wl + (size_t)dbase * I + lane * 4;  // warp's rows, lane's 16B
    const float* cblk  = Cl;                                  // staged via ring

    // Prime: always 3 committed groups (empty commits keep counting uniform).
#pragma unroll
    for (int p = 0; p < 3; ++p) {
        if (p < NS)
            stage_cursed<M, I>(smem_u32 + (uint32_t)p * SLOTB, cblk, p * S, tid);
        cp_commit();
    }

    // Weight prefetch for stage 0.
    ull w01[RW], w23[RW], n01[RW], n23[RW];
    load_w<I>(w01, w23, wlane, 0);

    for (int s = 0; s < NS; ++s) {
        cp_wait<2>();          // slot s resident (own groups); barrier publishes all
        __syncthreads();

        // Issue next stage's weight loads first (independent of compute below).
        if (s + 1 < NS)
            load_w<I>(n01, n23, wlane, (s + 1) * S);

        const float* cbuf = smem + (s & 3) * CSLOT_F + (g * MGV) * S + lane * 4;

#pragma unroll
        for (int j = 0; j < MGV; ++j) {
            const double2 cd = *reinterpret_cast<const double2*>(cbuf + j * S);
            const ull c01 = __double_as_longlong(cd.x);
            const ull c23 = __double_as_longlong(cd.y);
#pragma unroll
            for (int t = 0; t < RW; ++t) {
                ffma2(acc2[t][j], w01[t], c01);
                ffma2(acc2[t][j], w23[t], c23);
            }
        }

        // Prefetch cursed stage s+3 into slot (s+3)&3 = (s-1)&3: its readers
        // finished before the barrier above. Commit unconditionally.
        if (s + 3 < NS)
            stage_cursed<M, I>(smem_u32 + (uint32_t)((s + 3) & 3) * SLOTB,
                               cblk, (s + 3) * S, tid);
        cp_commit();

        // Rotate weight buffers.
#pragma unroll
        for (int t = 0; t < RW; ++t) { w01[t] = n01[t]; w23[t] = n23[t]; }
    }

    // Fold f32x2 pairs, butterfly-reduce across lanes, scatter stores.
#pragma unroll
    for (int t = 0; t < RW; ++t)
#pragma unroll
        for (int j = 0; j < MGV; ++j) {
            float v = hsum2(acc2[t][j]);
            v += __shfl_xor_sync(0xffffffffu, v, 16);
            v += __shfl_xor_sync(0xffffffffu, v, 8);
            v += __shfl_xor_sync(0xffffffffu, v, 4);
            v += __shfl_xor_sync(0xffffffffu, v, 2);
            v += __shfl_xor_sync(0xffffffffu, v, 1);
            if (lane == t * MGV + j) {
                const int jj = g * MGV + j;       // global vec index
                int m, k;
                if (IS_MLP) {
                    const int mi = jj >> 2;        // 0,1,2 -> gate, up, down
                    m = (mi == 2) ? 6 : (3 + mi);  // gate=3, up=4, down=6
                    k = jj & 3;
                } else {
                    m = MFIX;
                    k = jj;
                }
                const size_t row = ((size_t)(l * 7 + m) * 2 + 1) * Kc + k;
                out[row * Dc + (size_t)(dbase + t)] = v;
            }
        }
}

// Block segments (16 d-rows per proj block, 2048 blocks per matrix):
//   [0,2048) mlp  [2048,4096) q  [4096,6144) o  [6144,8192) k
//   [8192,10240) v  [10240,10496) residual copy
extern "C" __global__ void __launch_bounds__(256, 2)
both_sides_fused(const float* __restrict__ residual,
                 const float* __restrict__ cq, const float* __restrict__ ck,
                 const float* __restrict__ cv, const float* __restrict__ co,
                 const float* __restrict__ cm,
                 const float* __restrict__ Wq, const float* __restrict__ Wk,
                 const float* __restrict__ Wv, const float* __restrict__ Wo,
                 const float* __restrict__ Wd,
                 float* __restrict__ out)
{
    __shared__ __align__(16) float smem[NSLOT][CSLOT_F];   // 24 KB

    int b = blockIdx.x;
    if (b < 2048) {                                   // mlp (heaviest first)
        const int l = b >> 6, d0 = (b & 63) * ROWS_BLK;
        proj_tile<12, FFc, true, 0>(Wd + (size_t)l * Dc * FFc,
                                    cm + (size_t)l * 3 * Kc * FFc,
                                    out, &smem[0][0], l, d0);
    } else if (b < 4096) {                            // q (m=0)
        b -= 2048;
        const int l = b >> 6, d0 = (b & 63) * ROWS_BLK;
        proj_tile<4, QOc, false, 0>(Wq + (size_t)l * Dc * QOc,
                                    cq + (size_t)l * Kc * QOc,
                                    out, &smem[0][0], l, d0);
    } else if (b < 6144) {                            // o (m=5)
        b -= 4096;
        const int l = b >> 6, d0 = (b & 63) * ROWS_BLK;
        proj_tile<4, QOc, false, 5>(Wo + (size_t)l * Dc * QOc,
                                    co + (size_t)l * Kc * QOc,
                                    out, &smem[0][0], l, d0);
    } else if (b < 8192) {                            // k (m=1)
        b -= 6144;
        const int l = b >> 6, d0 = (b & 63) * ROWS_BLK;
        proj_tile<4, KVc, false, 1>(Wk + (size_t)l * Dc * KVc,
                                    ck + (size_t)l * Kc * KVc,
                                    out, &smem[0][0], l, d0);
    } else if (b < 10240) {                           // v (m=2)
        b -= 8192;
        const int l = b >> 6, d0 = (b & 63) * ROWS_BLK;
        proj_tile<4, KVc, false, 2>(Wv + (size_t)l * Dc * KVc,
                                    cv + (size_t)l * Kc * KVc,
                                    out, &smem[0][0], l, d0);
    } else {                                          // residual copy (s=0 rows)
        const float4* r4 = reinterpret_cast<const float4*>(residual);
        float4* o4 = reinterpret_cast<float4*>(out);
        const int nf4 = Lc * 7 * Kc * Dc / 4;         // 229376 float4
        for (int i = (b - 10240) * 256 + (int)threadIdx.x; i < nf4; i += 256 * 256) {
            const int chunk  = i >> 10;
            const int within = i & 1023;
            o4[(size_t)chunk * 2048 + within] = r4[i];
        }
    }
}

extern "C" void kernel_launch(void* const* d_in, const int* in_sizes, int n_in,
                              void* d_out, int out_size)
{
    const float* residual = (const float*)d_in[0];
    const float* cq       = (const float*)d_in[1];
    const float* ck       = (const float*)d_in[2];
    const float* cv       = (const float*)d_in[3];
    const float* co       = (const float*)d_in[4];
    const float* cm       = (const float*)d_in[5];
    const float* Wq       = (const float*)d_in[6];
    const float* Wk       = (const float*)d_in[7];
    const float* Wv       = (const float*)d_in[8];
    const float* Wo       = (const float*)d_in[9];
    const float* Wd       = (const float*)d_in[10];
    float* out            = (float*)d_out;

    both_sides_fused<<<10496, 256>>>(residual, cq, ck, cv, co, cm,
                                     Wq, Wk, Wv, Wo, Wd, out);
}

// round 8
// speedup vs baseline: 1.1549x; 1.1549x over previous
#include <cuda_runtime.h>
#include <cstdint>

// Problem constants
static constexpr int Lc  = 32;
static constexpr int Kc  = 4;
static constexpr int Dc  = 1024;
static constexpr int QOc = 1024;
static constexpr int KVc = 256;
static constexpr int FFc = 2816;

typedef unsigned long long ull;

// Scratch for per-slice partial sums (device globals: allowed scratch).
// scratchM[l][s(11)][j(12)][d(1024)], scratchQ/O[l][s(4)][k(4)][d(1024)]
__device__ float scratchM[32 * 11 * 12 * 1024];
__device__ float scratchQ[32 * 4 * 4 * 1024];
__device__ float scratchO[32 * 4 * 4 * 1024];

// ---------------- f32x2 packed ops (sm_103a) ----------------
__device__ __forceinline__ ull mul2(ull a, ull b) {
    ull d; asm("mul.rn.f32x2 %0, %1, %2;" : "=l"(d) : "l"(a), "l"(b)); return d;
}
__device__ __forceinline__ void fma2(ull& acc, ull a, ull b) {
    asm("fma.rn.f32x2 %0, %1, %2, %0;" : "+l"(acc) : "l"(a), "l"(b));
}
__device__ __forceinline__ float hsum2(ull v) {
    return __uint_as_float((uint32_t)v) + __uint_as_float((uint32_t)(v >> 32));
}

// =====================================================================
// Kernel A: warp-autonomous projection partials.
// Warp unit = (matrix, layer, 256-col slice, 256-row chunk, 4-vec group).
// Streams 256 rows x 1KB of weights; cursed vecs stationary in registers.
// Units: MLP 4224 | Q 512 | O 512 | K 128 | V 128  = 5504 = 688 blocks x 8.
// =====================================================================
extern "C" __global__ void __launch_bounds__(256, 2)
proj_partials(const float* __restrict__ cq, const float* __restrict__ ck,
              const float* __restrict__ cv, const float* __restrict__ co,
              const float* __restrict__ cm,
              const float* __restrict__ Wq, const float* __restrict__ Wk,
              const float* __restrict__ Wv, const float* __restrict__ Wo,
              const float* __restrict__ Wd,
              float* __restrict__ out)
{
    const int lane = threadIdx.x & 31;
    const int u    = blockIdx.x * 8 + (threadIdx.x >> 5);

    const float* wp;   // weight base: row0, +c0, +lane*4
    const float* cp;   // cursed base: vec0 of group, +c0, +lane*4
    float*       sp;   // store base (scratch or out), lane adds v*1024 + row
    int I;

    if (u < 4224) {                       // MLP (W_down, 12 vecs in 3 groups)
        int vg = u % 3, t = u / 3;
        const int rc = t & 3; t >>= 2;
        const int s = t % 11, l = t / 11;
        I = FFc;
        const int c0 = s * 256, row0 = rc * 256;
        wp = Wd + ((size_t)l * Dc + row0) * FFc + c0 + lane * 4;
        cp = cm + ((size_t)l * 12 + vg * 4) * FFc + c0 + lane * 4;
        sp = scratchM + (size_t)((l * 11 + s) * 12 + vg * 4) * 1024 + row0;
    } else if (u < 5248) {                // Q or O
        int t = u - 4224;
        const bool isO = t >= 512; if (isO) t -= 512;
        const int rc = t & 3; t >>= 2;
        const int s = t & 3, l = t >> 2;
        I = QOc;
        const int c0 = s * 256, row0 = rc * 256;
        const float* W = isO ? Wo : Wq;
        const float* C = isO ? co : cq;
        wp = W + ((size_t)l * Dc + row0) * QOc + c0 + lane * 4;
        cp = C + (size_t)l * 4 * QOc + c0 + lane * 4;
        sp = (isO ? scratchO : scratchQ) + (size_t)((l * 4 + s) * 4) * 1024 + row0;
    } else {                              // K or V (I=256: direct output)
        int t = u - 5248;
        const bool isV = t >= 128; if (isV) t -= 128;
        const int rc = t & 3, l = t >> 2;
        I = KVc;
        const int row0 = rc * 256;
        const float* W = isV ? Wv : Wk;
        const float* C = isV ? cv : ck;
        wp = W + ((size_t)l * Dc + row0) * KVc + lane * 4;
        cp = C + (size_t)l * 4 * KVc + lane * 4;
        const int m = isV ? 2 : 1;
        sp = out + (size_t)(((l * 7 + m) * 2 + 1) * 4) * 1024 + row0;
    }

    // Cursed vectors stationary in registers: 4 vecs x 8 floats/lane.
    ull ca01[4], ca23[4], cb01[4], cb23[4];
#pragma unroll
    for (int v = 0; v < 4; ++v) {
        const double2 x = *reinterpret_cast<const double2*>(cp + (size_t)v * I);
        const double2 y = *reinterpret_cast<const double2*>(cp + (size_t)v * I + 128);
        ca01[v] = __double_as_longlong(x.x);
        ca23[v] = __double_as_longlong(x.y);
        cb01[v] = __double_as_longlong(y.x);
        cb23[v] = __double_as_longlong(y.y);
    }

    // 4-deep weight row pipeline.
    ull w[4][4];   // [slot][a01,a23,b01,b23]
#pragma unroll
    for (int r = 0; r < 4; ++r) {
        const double2 x = *reinterpret_cast<const double2*>(wp + (size_t)r * I);
        const double2 y = *reinterpret_cast<const double2*>(wp + (size_t)r * I + 128);
        w[r][0] = __double_as_longlong(x.x);
        w[r][1] = __double_as_longlong(x.y);
        w[r][2] = __double_as_longlong(y.x);
        w[r][3] = __double_as_longlong(y.y);
    }

    const bool lo16 = lane < 16;
    const bool bit3 = (lane & 8) != 0;
    float mine = 0.f;

    for (int g = 0; g < 32; ++g) {
#pragma unroll
        for (int rr = 0; rr < 8; ++rr) {
            const int r    = g * 8 + rr;
            const int slot = rr & 3;

            // Consume current row's weights into locals.
            const ull a01 = w[slot][0], a23 = w[slot][1];
            const ull b01 = w[slot][2], b23 = w[slot][3];

            // Prefetch row r+4 (wrapped for tail-safety; values unused past end).
            {
                const float* wr = wp + (size_t)((r + 4) & 255) * I;
                const double2 x = *reinterpret_cast<const double2*>(wr);
                const double2 y = *reinterpret_cast<const double2*>(wr + 128);
                w[slot][0] = __double_as_longlong(x.x);
                w[slot][1] = __double_as_longlong(x.y);
                w[slot][2] = __double_as_longlong(y.x);
                w[slot][3] = __double_as_longlong(y.y);
            }

            // Per-vec dot partial over this lane's 8 columns.
            float f0, f1, f2, f3;
            {
                ull t0 = mul2(a01, ca01[0]); fma2(t0, a23, ca23[0]);
                fma2(t0, b01, cb01[0]);      fma2(t0, b23, cb23[0]);
                ull t1 = mul2(a01, ca01[1]); fma2(t1, a23, ca23[1]);
                fma2(t1, b01, cb01[1]);      fma2(t1, b23, cb23[1]);
                ull t2 = mul2(a01, ca01[2]); fma2(t2, a23, ca23[2]);
                fma2(t2, b01, cb01[2]);      fma2(t2, b23, cb23[2]);
                ull t3 = mul2(a01, ca01[3]); fma2(t3, a23, ca23[3]);
                fma2(t3, b01, cb01[3]);      fma2(t3, b23, cb23[3]);
                f0 = hsum2(t0); f1 = hsum2(t1); f2 = hsum2(t2); f3 = hsum2(t3);
            }

            // Split-tree 32-lane reduction of 4 values (~6 shfl).
            // After: value v's full sum lives on lanes [v*8, v*8+8).
            const float ka = lo16 ? f0 : f2, sa = lo16 ? f2 : f0;
            const float g0 = ka + __shfl_xor_sync(0xffffffffu, sa, 16);
            const float kb = lo16 ? f1 : f3, sb = lo16 ? f3 : f1;
            const float g1 = kb + __shfl_xor_sync(0xffffffffu, sb, 16);
            const float kc = bit3 ? g1 : g0, sc = bit3 ? g0 : g1;
            float h = kc + __shfl_xor_sync(0xffffffffu, sc, 8);
            h += __shfl_xor_sync(0xffffffffu, h, 4);
            h += __shfl_xor_sync(0xffffffffu, h, 2);
            h += __shfl_xor_sync(0xffffffffu, h, 1);

            // Lane v*8 + rr keeps value (row=rr, vec=v).
            if ((lane & 7) == rr) mine = h;
        }
        // One coalesced-ish store per 8 rows: lane -> (v = lane>>3, r = lane&7).
        sp[(size_t)(lane >> 3) * 1024 + g * 8 + (lane & 7)] = mine;
    }
}

// =====================================================================
// Kernel B: reduce partials over slices, write outputs, residual copy.
// Segments (256-thr blocks):
//   [0, 393216)       MLP reduce (11 partials)   -> 1536 blocks
//   [393216, 524288)  Q reduce (4 partials)      -> 512 blocks
//   [524288, 655360)  O reduce (4 partials)      -> 512 blocks
//   [655360, 884736)  residual copy (float4)     -> 896 blocks
// =====================================================================
extern "C" __global__ void __launch_bounds__(256)
reduce_out(const float* __restrict__ residual, float* __restrict__ out)
{
    const int x = blockIdx.x * 256 + threadIdx.x;

    if (x < 393216) {                       // MLP
        const int d = x & 1023;
        int t = x >> 10;
        const int j = t % 12, l = t / 12;
        const float* p = scratchM + (size_t)(l * 11 * 12 + j) * 1024 + d;
        float s = 0.f;
#pragma unroll
        for (int si = 0; si < 11; ++si) s += p[(size_t)si * 12 * 1024];
        const int mi = j >> 2;
        const int m  = (mi == 2) ? 6 : (3 + mi);
        const int k  = j & 3;
        out[(size_t)(((l * 7 + m) * 2 + 1) * 4 + k) * 1024 + d] = s;
    } else if (x < 524288) {                // Q (m=0)
        const int y = x - 393216;
        const int d = y & 1023;
        int t = y >> 10;
        const int k = t & 3, l = t >> 2;
        const float* p = scratchQ + (size_t)(l * 16 + k) * 1024 + d;
        float s = 0.f;
#pragma unroll
        for (int si = 0; si < 4; ++si) s += p[(size_t)si * 4 * 1024];
        out[(size_t)(((l * 7 + 0) * 2 + 1) * 4 + k) * 1024 + d] = s;
    } else if (x < 655360) {                // O (m=5)
        const int y = x - 524288;
        const int d = y & 1023;
        int t = y >> 10;
        const int k = t & 3, l = t >> 2;
        const float* p = scratchO + (size_t)(l * 16 + k) * 1024 + d;
        float s = 0.f;
#pragma unroll
        for (int si = 0; si < 4; ++si) s += p[(size_t)si * 4 * 1024];
        out[(size_t)(((l * 7 + 5) * 2 + 1) * 4 + k) * 1024 + d] = s;
    } else {                                // residual copy (s=0 rows)
        const int i = x - 655360;           // < 229376 float4
        const float4* r4 = reinterpret_cast<const float4*>(residual);
        float4* o4 = reinterpret_cast<float4*>(out);
        const int chunk  = i >> 10;         // (l,m) chunk: 1024 float4 each
        const int within = i & 1023;
        o4[(size_t)chunk * 2048 + within] = r4[i];
    }
}

extern "C" void kernel_launch(void* const* d_in, const int* in_sizes, int n_in,
                              void* d_out, int out_size)
{
    const float* residual = (const float*)d_in[0];
    const float* cq       = (const float*)d_in[1];
    const float* ck       = (const float*)d_in[2];
    const float* cv       = (const float*)d_in[3];
    const float* co       = (const float*)d_in[4];
    const float* cm       = (const float*)d_in[5];
    const float* Wq       = (const float*)d_in[6];
    const float* Wk       = (const float*)d_in[7];
    const float* Wv       = (const float*)d_in[8];
    const float* Wo       = (const float*)d_in[9];
    const float* Wd       = (const float*)d_in[10];
    float* out            = (float*)d_out;

    proj_partials<<<688, 256>>>(cq, ck, cv, co, cm,
                                Wq, Wk, Wv, Wo, Wd, out);
    reduce_out<<<3456, 256>>>(residual, out);
}